// round 2
// baseline (speedup 1.0000x reference)
#include <cuda_runtime.h>
#include <cstdint>

// Gate pipeline:
//   g = conv(inputs, w; stride 4, VALID)  -> [64,1,128,128]
//   per-batch find K-th largest (K=4096 of 16384) -> threshold key per batch
//   out[b,c,y,x] = in * (g >= thr ? g : 0), gate upsampled 4x, bcast 3 ch
//
// Scratch: gate map 4 MB (L2-resident) + 64 threshold keys.
__device__ float    d_gate[64 * 16384];
__device__ unsigned d_thr[64];

__device__ __forceinline__ unsigned f2key(float f) {
    unsigned u = __float_as_uint(f);
    return (u & 0x80000000u) ? ~u : (u | 0x80000000u);  // monotone float->uint
}

// ---------------------------------------------------------------------------
// Kernel 1: 4x4 stride-4 conv, 3->1 channels. One thread per gate pixel.
// 12 coalesced float4 loads per thread. DRAM-bound at ~80% (measured R1).
// ---------------------------------------------------------------------------
__global__ void gate_conv_kernel(const float4* __restrict__ in,
                                 const float* __restrict__ wk) {
    __shared__ float4 w[12];
    int t = threadIdx.x;
    if (t < 12) w[t] = reinterpret_cast<const float4*>(wk)[t];
    __syncthreads();

    int idx = blockIdx.x * blockDim.x + t;      // [0, 64*16384)
    int x = idx & 127;
    int y = (idx >> 7) & 127;
    int b = idx >> 14;

    const float4* base = in + (size_t)b * 196608 + x;

    float sum = 0.0f;
#pragma unroll
    for (int c = 0; c < 3; c++) {
#pragma unroll
        for (int i = 0; i < 4; i++) {
            float4 v = base[c * 65536 + (4 * y + i) * 128];
            float4 ww = w[c * 4 + i];
            sum += v.x * ww.x + v.y * ww.y + v.z * ww.z + v.w * ww.w;
        }
    }
    d_gate[idx] = sum;
}

// ---------------------------------------------------------------------------
// Kernel 2: per-batch exact K-th-largest key via MSB-first radix select.
// Keys cached in shared (64KB); warp-aggregated histogram atomics
// (__match_any_sync) to kill hot-bin contention from clustered exponents.
// Writes ONLY the threshold key — no gate rewrite pass.
// ---------------------------------------------------------------------------
__global__ void gate_select_kernel() {
    __shared__ unsigned keys[16384];
    __shared__ unsigned hist[256];
    __shared__ unsigned s_prefix;
    __shared__ int s_k;

    const int row = blockIdx.x;
    const int t = threadIdx.x;          // blockDim = 512
    const int lane = t & 31;
    const float* grow = d_gate + row * 16384;

    // stage keys in smem (reads are L2-hot: conv just wrote them)
#pragma unroll
    for (int i = 0; i < 32; i++)
        keys[t + i * 512] = f2key(grow[t + i * 512]);

    if (t == 0) { s_prefix = 0u; s_k = 4096; }
    __syncthreads();

#pragma unroll
    for (int pass = 0; pass < 4; pass++) {
        const int shift = 24 - 8 * pass;
        if (t < 256) hist[t] = 0u;
        __syncthreads();

        const unsigned pmask = pass ? (0xFFFFFFFFu << (32 - 8 * pass)) : 0u;
        const unsigned prefix = s_prefix;

#pragma unroll
        for (int i = 0; i < 32; i++) {
            unsigned u = keys[t + i * 512];
            // non-matching threads get an out-of-range bin so the whole warp
            // can participate in match_any
            unsigned bin = ((u & pmask) == prefix) ? ((u >> shift) & 0xFFu)
                                                   : 0xFFFFFFFFu;
            unsigned same = __match_any_sync(0xFFFFFFFFu, bin);
            if (bin != 0xFFFFFFFFu && lane == (__ffs(same) - 1))
                atomicAdd(&hist[bin], __popc(same));
        }
        __syncthreads();

        if (t == 0) {
            int k = s_k;
            int bin = 255;
            for (;;) {
                int c = (int)hist[bin];
                if (c >= k) break;
                k -= c;
                bin--;
            }
            s_prefix = prefix | ((unsigned)bin << shift);
            s_k = k;
        }
        __syncthreads();
    }

    if (t == 0) d_thr[row] = s_prefix;  // exact key of the K-th largest value
}

// ---------------------------------------------------------------------------
// Kernel 3: out = in * gate (thresholded). 75% of gate cells are dead ->
// skip the input load there and write zeros (saves ~55% of read sectors).
// One float4 (4 cols) == one gate cell, so the keep/kill branch is per-thread.
// ---------------------------------------------------------------------------
__global__ void gate_mul_kernel(const float4* __restrict__ in,
                                float4* __restrict__ out) {
    int idx = blockIdx.x * blockDim.x + threadIdx.x;  // [0, 64*3*512*128)
    int x4 = idx & 127;            // float4 col == gate col
    int y  = (idx >> 7) & 511;     // image row
    int bc = idx >> 16;            // b*3 + c   (uniform within a block)
    int b  = bc / 3;

    unsigned thr = d_thr[b];
    float gv = d_gate[b * 16384 + (y >> 2) * 128 + x4];

    float4 v;
    if (f2key(gv) >= thr) {
        v = in[idx];
        v.x *= gv; v.y *= gv; v.z *= gv; v.w *= gv;
    } else {
        v = make_float4(0.f, 0.f, 0.f, 0.f);
    }
    out[idx] = v;
}

// ---------------------------------------------------------------------------
extern "C" void kernel_launch(void* const* d_in, const int* in_sizes, int n_in,
                              void* d_out, int out_size) {
    const float* inp = (const float*)d_in[0];
    const float* wk  = (const float*)d_in[1];
    if (n_in >= 2 && in_sizes[0] == 48) {  // defensive: swap if order flipped
        inp = (const float*)d_in[1];
        wk  = (const float*)d_in[0];
    }

    gate_conv_kernel<<<4096, 256>>>((const float4*)inp, wk);
    gate_select_kernel<<<64, 512>>>();
    gate_mul_kernel<<<49152, 256>>>((const float4*)inp, (float4*)d_out);
}